// round 1
// baseline (speedup 1.0000x reference)
#include <cuda_runtime.h>
#include <cstdint>

#define B_   128
#define T_   512
#define DIM_ 256
#define E_   512
#define H_   512

// ---------------- device scratch (no allocations allowed) ----------------
__device__ float g_xe[(size_t)B_ * T_ * E_];            // 128 MB
__device__ float g_gates[(size_t)T_ * 4 * B_ * H_];     // 512 MB, layout [t][g][b][h]
__device__ float g_h[2 * B_ * H_];                      // double-buffered hidden state
__device__ float g_part[2 * 4 * B_ * H_];               // K-split partial pre-activations [kb][g][b][h]
__device__ unsigned g_pairflag[64];                     // per (rt,ct) tile
__device__ unsigned g_grpcnt[4];
__device__ unsigned g_grpgen[4];

// ---------------- generic SGEMM: C = A @ W^T + bias ----------------
// MODE 0: A = param (x [65536 x 256]), W=We, out -> g_xe[m*512+n]
// MODE 1: A = g_xe [65536 x 512], W selected by blockIdx.z (i,f,g,o),
//         out -> g_gates[((t*4+g)*B + b)*H + n],  m = b*T + t
template <int MODE>
__global__ void __launch_bounds__(256)
sgemm_bias(const float* __restrict__ A,
           const float* __restrict__ W0, const float* __restrict__ W1,
           const float* __restrict__ W2, const float* __restrict__ W3,
           const float* __restrict__ b0, const float* __restrict__ b1,
           const float* __restrict__ b2, const float* __restrict__ b3,
           int K)
{
    __shared__ float As[8][128];
    __shared__ float Bs[8][128];

    const int tid = threadIdx.x;
    const int m0 = blockIdx.y * 128;
    const int n0 = blockIdx.x * 128;
    const int gz = blockIdx.z;

    const float* Ap = (MODE == 0) ? A : g_xe;
    const float* Wsel = W0;
    const float* bsel = b0;
    if (MODE == 1) {
        if (gz == 1) { Wsel = W1; bsel = b1; }
        else if (gz == 2) { Wsel = W2; bsel = b2; }
        else if (gz == 3) { Wsel = W3; bsel = b3; }
    }

    const int lrow = tid >> 1;          // 0..127
    const int lcol = (tid & 1) * 4;     // 0 or 4

    float acc[8][8];
#pragma unroll
    for (int i = 0; i < 8; i++)
#pragma unroll
        for (int j = 0; j < 8; j++) acc[i][j] = 0.0f;

    const int tx = tid & 15;
    const int ty = tid >> 4;

    for (int kt = 0; kt < K; kt += 8) {
        float4 av = *(const float4*)(Ap + (size_t)(m0 + lrow) * K + kt + lcol);
        float4 wv = *(const float4*)(Wsel + (size_t)(n0 + lrow) * K + kt + lcol);
        As[lcol + 0][lrow] = av.x; As[lcol + 1][lrow] = av.y;
        As[lcol + 2][lrow] = av.z; As[lcol + 3][lrow] = av.w;
        Bs[lcol + 0][lrow] = wv.x; Bs[lcol + 1][lrow] = wv.y;
        Bs[lcol + 2][lrow] = wv.z; Bs[lcol + 3][lrow] = wv.w;
        __syncthreads();

#pragma unroll
        for (int k = 0; k < 8; k++) {
            float ar[8], br[8];
            *(float4*)(ar)     = *(const float4*)&As[k][ty * 8];
            *(float4*)(ar + 4) = *(const float4*)&As[k][ty * 8 + 4];
            *(float4*)(br)     = *(const float4*)&Bs[k][tx * 8];
            *(float4*)(br + 4) = *(const float4*)&Bs[k][tx * 8 + 4];
#pragma unroll
            for (int i = 0; i < 8; i++)
#pragma unroll
                for (int j = 0; j < 8; j++) acc[i][j] += ar[i] * br[j];
        }
        __syncthreads();
    }

#pragma unroll
    for (int i = 0; i < 8; i++) {
        const int m = m0 + ty * 8 + i;
#pragma unroll
        for (int j = 0; j < 8; j++) {
            const int n = n0 + tx * 8 + j;
            float v = acc[i][j] + bsel[n];
            if (MODE == 0) {
                g_xe[(size_t)m * E_ + n] = v;
            } else {
                const int b = m >> 9;       // T_ = 512
                const int t = m & 511;
                g_gates[((size_t)(t * 4 + gz) * B_ + b) * H_ + n] = v;
            }
        }
    }
}

// ---------------- persistent recurrence kernel ----------------
// 128 blocks: bid = (rt*16 + ct)*2 + kb ; rt in 0..3 (32-row tiles of B),
// ct in 0..15 (32-col tiles of H), kb in 0..1 (K halves of 256).
// Each block keeps its R slice [256k x 4g x 32c] (128 KB) in smem for all steps.

__device__ __forceinline__ float sigmoidf_(float x) {
    return 1.0f / (1.0f + __expf(-x));
}

__device__ __forceinline__ void group_barrier(int grp, unsigned nb) {
    __threadfence();
    __syncthreads();
    if (threadIdx.x == 0) {
        unsigned gen0 = atomicAdd(&g_grpgen[grp], 0u);
        unsigned old = atomicAdd(&g_grpcnt[grp], 1u);
        if (old == nb - 1u) {
            atomicExch(&g_grpcnt[grp], 0u);
            __threadfence();
            atomicAdd(&g_grpgen[grp], 1u);
        } else {
            while (atomicAdd(&g_grpgen[grp], 0u) == gen0) __nanosleep(40);
        }
        __threadfence();
    }
    __syncthreads();
}

__global__ void __launch_bounds__(256, 1)
lstm_recurrence(const float* __restrict__ h0, const float* __restrict__ c0,
                const float* __restrict__ R0, const float* __restrict__ R1,
                const float* __restrict__ R2, const float* __restrict__ R3,
                float* __restrict__ out)
{
    extern __shared__ float smem[];
    float* R_s = smem;                 // [256][128]  (k-major, inner = c*4+g)
    float* h_s = smem + 256 * 128;     // [256][32]   (k-major, inner = local row)

    const int tid = threadIdx.x;
    const int bid = blockIdx.x;
    const int kb = bid & 1;
    const int ct = (bid >> 1) & 15;
    const int rt = bid >> 5;
    const int r0 = rt * 32;
    const int c0c = ct * 32;
    const int k0 = kb * 256;
    const int pf = (rt << 4) | ct;

    // pairwise-flag base (read before any increments of this run)
    unsigned pairbase = 0;
    if (tid == 0) pairbase = atomicAdd(&g_pairflag[pf], 0u);

    // ---- load resident R slice into smem (one-time) ----
    {
        const float* Rg;
#pragma unroll
        for (int gg = 0; gg < 4; gg++) {
            if (gg == 0) Rg = R0; else if (gg == 1) Rg = R1;
            else if (gg == 2) Rg = R2; else Rg = R3;
            for (int i = tid; i < 32 * 256; i += 256) {
                const int c = i >> 8;
                const int k = i & 255;
                R_s[k * 128 + c * 4 + gg] = Rg[(size_t)(c0c + c) * H_ + k0 + k];
            }
        }
    }

    // ---- init c registers and h buffer 0 ----
    float creg[2];
#pragma unroll
    for (int j = 0; j < 2; j++) {
        const int e = tid + j * 256;
        const int lr = e >> 5, cc = e & 31;
        const int b = r0 + kb * 16 + lr;
        const int hcol = c0c + cc;
        creg[j] = c0[(size_t)b * H_ + hcol];
        g_h[(size_t)b * H_ + hcol] = h0[(size_t)b * H_ + hcol];
    }
    group_barrier(rt, 32u);

    const int cc_g = tid & 31;       // GEMM col within tile
    const int rg = tid >> 5;         // GEMM row group (4 rows each)
    const float4* Rs4 = (const float4*)R_s;
    const float4* Hs4 = (const float4*)h_s;
    float* pp = g_part + (size_t)kb * 4 * B_ * H_;

    for (int t = 0; t < T_; t++) {
        // ---- stage h_prev tile into smem ----
        {
            const int r = tid & 31;
            const int kq = tid >> 5;
            const float* src = g_h + (size_t)(t & 1) * B_ * H_
                               + (size_t)(r0 + r) * H_ + k0 + kq * 32;
#pragma unroll
            for (int i = 0; i < 32; i++)
                h_s[(kq * 32 + i) * 32 + r] = src[i];
        }
        __syncthreads();

        // ---- partial GEMM: [32 rows x 32 cols x 4 gates], K = 256 ----
        float acc[16];
#pragma unroll
        for (int i = 0; i < 16; i++) acc[i] = 0.0f;

#pragma unroll 8
        for (int k = 0; k < 256; k++) {
            const float4 rv = Rs4[k * 32 + cc_g];
            const float4 hv = Hs4[k * 8 + rg];
            acc[0]  += hv.x * rv.x; acc[1]  += hv.x * rv.y;
            acc[2]  += hv.x * rv.z; acc[3]  += hv.x * rv.w;
            acc[4]  += hv.y * rv.x; acc[5]  += hv.y * rv.y;
            acc[6]  += hv.y * rv.z; acc[7]  += hv.y * rv.w;
            acc[8]  += hv.z * rv.x; acc[9]  += hv.z * rv.y;
            acc[10] += hv.z * rv.z; acc[11] += hv.z * rv.w;
            acc[12] += hv.w * rv.x; acc[13] += hv.w * rv.y;
            acc[14] += hv.w * rv.z; acc[15] += hv.w * rv.w;
        }

        // ---- store partials ----
#pragma unroll
        for (int r4 = 0; r4 < 4; r4++) {
            const size_t rowoff = (size_t)(r0 + rg * 4 + r4) * H_ + c0c + cc_g;
#pragma unroll
            for (int gg = 0; gg < 4; gg++)
                pp[((size_t)gg << 16) + rowoff] = acc[r4 * 4 + gg];
        }

        // ---- pairwise sync with the other K-half of this tile ----
        __threadfence();
        __syncthreads();
        if (tid == 0) {
            atomicAdd(&g_pairflag[pf], 1u);
            const unsigned target = pairbase + 2u * (unsigned)(t + 1);
            while ((int)(atomicAdd(&g_pairflag[pf], 0u) - target) < 0) __nanosleep(30);
            __threadfence();
        }
        __syncthreads();

        // ---- elementwise LSTM cell update (rows split by kb) ----
#pragma unroll
        for (int j = 0; j < 2; j++) {
            const int e = tid + j * 256;
            const int lr = e >> 5, cc = e & 31;
            const int b = r0 + kb * 16 + lr;
            const int hcol = c0c + cc;
            const size_t bh = (size_t)b * H_ + hcol;
            const size_t goff = (size_t)(t * 4) * (B_ * H_);

            const float pi = g_gates[goff + 0 * (B_ * H_) + bh] + g_part[0 * (size_t)(B_ * H_) + bh] + g_part[4 * (size_t)(B_ * H_) + bh];
            const float pf_ = g_gates[goff + 1 * (B_ * H_) + bh] + g_part[1 * (size_t)(B_ * H_) + bh] + g_part[5 * (size_t)(B_ * H_) + bh];
            const float pg = g_gates[goff + 2 * (B_ * H_) + bh] + g_part[2 * (size_t)(B_ * H_) + bh] + g_part[6 * (size_t)(B_ * H_) + bh];
            const float po = g_gates[goff + 3 * (B_ * H_) + bh] + g_part[3 * (size_t)(B_ * H_) + bh] + g_part[7 * (size_t)(B_ * H_) + bh];

            const float ig = sigmoidf_(pi);
            const float fg = sigmoidf_(pf_);
            const float gg = tanhf(pg);
            const float og = sigmoidf_(po);
            creg[j] = gg * ig + fg * creg[j];
            const float hn = og * tanhf(creg[j]);

            g_h[(size_t)((t + 1) & 1) * B_ * H_ + bh] = hn;
            out[(size_t)b * T_ * H_ + (size_t)t * H_ + hcol] = hn;
            if (t == T_ - 1) {
                const size_t BTH = (size_t)B_ * T_ * H_;
                out[BTH + bh] = hn;
                out[BTH + (size_t)B_ * H_ + bh] = creg[j];
            }
        }

        // ---- group barrier: h[t+1] for this row-group fully written ----
        group_barrier(rt, 32u);
    }
}

// ---------------- launch ----------------
extern "C" void kernel_launch(void* const* d_in, const int* in_sizes, int n_in,
                              void* d_out, int out_size)
{
    (void)in_sizes; (void)n_in; (void)out_size;
    const float* x  = (const float*)d_in[0];
    const float* h0 = (const float*)d_in[1];
    const float* c0 = (const float*)d_in[2];
    const float* We = (const float*)d_in[3];
    const float* be = (const float*)d_in[4];
    const float* Wf = (const float*)d_in[5];
    const float* bf = (const float*)d_in[6];
    const float* Wi = (const float*)d_in[7];
    const float* bi = (const float*)d_in[8];
    const float* Wg = (const float*)d_in[9];
    const float* bg = (const float*)d_in[10];
    const float* Wo = (const float*)d_in[11];
    const float* bo = (const float*)d_in[12];
    const float* Rf = (const float*)d_in[13];
    const float* Ri = (const float*)d_in[14];
    const float* Rg = (const float*)d_in[15];
    const float* Ro = (const float*)d_in[16];
    float* out = (float*)d_out;

    cudaFuncSetAttribute(lstm_recurrence,
                         cudaFuncAttributeMaxDynamicSharedMemorySize, 163840);

    // xe = x @ We^T + be
    dim3 g1(E_ / 128, (B_ * T_) / 128, 1);
    sgemm_bias<0><<<g1, 256>>>(x, We, We, We, We, be, be, be, be, DIM_);

    // gate pre-activations (i,f,g,o) = xe @ W^T + b, stored [t][g][b][h]
    dim3 g2(H_ / 128, (B_ * T_) / 128, 4);
    sgemm_bias<1><<<g2, 256>>>(nullptr, Wi, Wf, Wg, Wo, bi, bf, bg, bo, E_);

    // persistent recurrence (gate order i,f,g,o)
    lstm_recurrence<<<128, 256, 163840>>>(h0, c0, Ri, Rf, Rg, Ro, out);
}

// round 2
// speedup vs baseline: 1.6048x; 1.6048x over previous
#include <cuda_runtime.h>
#include <cstdint>

#define B_   128
#define T_   512
#define DIM_ 256
#define E_   512
#define H_   512

// ---------------- device scratch ----------------
__device__ float g_xe[(size_t)B_ * T_ * E_];                 // [m=b*T+t][e]
__device__ float g_gates[(size_t)T_ * B_ * 4 * H_];          // [t][b][gate][hcol]
__device__ float g_hP[2 * 16 * 64 * 32 * 2];                 // [buf][bn][ks][lane][2] (tf32 bits)
__device__ unsigned g_cnt2[4];
__device__ volatile unsigned g_gen2[4];

// ---------------- helpers ----------------
__device__ __forceinline__ unsigned tf32_(float f) {
    unsigned u;
    asm("cvt.rna.tf32.f32 %0, %1;" : "=r"(u) : "f"(f));
    return u;
}

__device__ __forceinline__ void mma_tf32(float* d, const unsigned* a, unsigned b0, unsigned b1) {
    asm volatile(
        "mma.sync.aligned.m16n8k8.row.col.f32.tf32.tf32.f32 "
        "{%0,%1,%2,%3}, {%4,%5,%6,%7}, {%8,%9}, {%0,%1,%2,%3};"
        : "+f"(d[0]), "+f"(d[1]), "+f"(d[2]), "+f"(d[3])
        : "r"(a[0]), "r"(a[1]), "r"(a[2]), "r"(a[3]), "r"(b0), "r"(b1));
}

__device__ __forceinline__ float sigmoidf_(float x) {
    return 1.0f / (1.0f + __expf(-x));
}

// ---------------- SGEMM: C = A @ W^T + bias (fp32, pre-pass) ----------------
// MODE 0: A = x [65536 x 256], W=We, out -> g_xe[m*512+n]
// MODE 1: A = g_xe [65536 x 512], W per blockIdx.z, out -> g_gates[t][b][gz][n]
template <int MODE>
__global__ void __launch_bounds__(256)
sgemm_bias(const float* __restrict__ A,
           const float* __restrict__ W0, const float* __restrict__ W1,
           const float* __restrict__ W2, const float* __restrict__ W3,
           const float* __restrict__ b0, const float* __restrict__ b1,
           const float* __restrict__ b2, const float* __restrict__ b3,
           int K)
{
    __shared__ float As[8][128];
    __shared__ float Bs[8][128];

    const int tid = threadIdx.x;
    const int m0 = blockIdx.y * 128;
    const int n0 = blockIdx.x * 128;
    const int gz = blockIdx.z;

    const float* Ap = (MODE == 0) ? A : g_xe;
    const float* Wsel = W0;
    const float* bsel = b0;
    if (MODE == 1) {
        if (gz == 1) { Wsel = W1; bsel = b1; }
        else if (gz == 2) { Wsel = W2; bsel = b2; }
        else if (gz == 3) { Wsel = W3; bsel = b3; }
    }

    const int lrow = tid >> 1;
    const int lcol = (tid & 1) * 4;

    float acc[8][8];
#pragma unroll
    for (int i = 0; i < 8; i++)
#pragma unroll
        for (int j = 0; j < 8; j++) acc[i][j] = 0.0f;

    const int tx = tid & 15;
    const int ty = tid >> 4;

    for (int kt = 0; kt < K; kt += 8) {
        float4 av = *(const float4*)(Ap + (size_t)(m0 + lrow) * K + kt + lcol);
        float4 wv = *(const float4*)(Wsel + (size_t)(n0 + lrow) * K + kt + lcol);
        As[lcol + 0][lrow] = av.x; As[lcol + 1][lrow] = av.y;
        As[lcol + 2][lrow] = av.z; As[lcol + 3][lrow] = av.w;
        Bs[lcol + 0][lrow] = wv.x; Bs[lcol + 1][lrow] = wv.y;
        Bs[lcol + 2][lrow] = wv.z; Bs[lcol + 3][lrow] = wv.w;
        __syncthreads();

#pragma unroll
        for (int k = 0; k < 8; k++) {
            float ar[8], br[8];
            *(float4*)(ar)     = *(const float4*)&As[k][ty * 8];
            *(float4*)(ar + 4) = *(const float4*)&As[k][ty * 8 + 4];
            *(float4*)(br)     = *(const float4*)&Bs[k][tx * 8];
            *(float4*)(br + 4) = *(const float4*)&Bs[k][tx * 8 + 4];
#pragma unroll
            for (int i = 0; i < 8; i++)
#pragma unroll
                for (int j = 0; j < 8; j++) acc[i][j] += ar[i] * br[j];
        }
        __syncthreads();
    }

#pragma unroll
    for (int i = 0; i < 8; i++) {
        const int m = m0 + ty * 8 + i;
        if (MODE == 0) {
#pragma unroll
            for (int j = 0; j < 8; j++) {
                const int n = n0 + tx * 8 + j;
                g_xe[(size_t)m * E_ + n] = acc[i][j] + bsel[n];
            }
        } else {
            const int b = m >> 9;
            const int t = m & 511;
            const int nb = n0 + tx * 8;
            float4 v0, v1;
            v0.x = acc[i][0] + bsel[nb + 0]; v0.y = acc[i][1] + bsel[nb + 1];
            v0.z = acc[i][2] + bsel[nb + 2]; v0.w = acc[i][3] + bsel[nb + 3];
            v1.x = acc[i][4] + bsel[nb + 4]; v1.y = acc[i][5] + bsel[nb + 5];
            v1.z = acc[i][6] + bsel[nb + 6]; v1.w = acc[i][7] + bsel[nb + 7];
            const size_t base = (((size_t)t * B_ + b) * 4 + gz) * H_ + nb;
            *(float4*)(g_gates + base)     = v0;
            *(float4*)(g_gates + base + 4) = v1;
        }
    }
}

// ---------------- group barrier (32 blocks per batch-group) ----------------
__device__ __forceinline__ void group_barrier32(int ng) {
    __syncthreads();
    if (threadIdx.x == 0) {
        unsigned g = g_gen2[ng];
        __threadfence();
        unsigned old = atomicAdd(&g_cnt2[ng], 1u);
        if (old == 31u) {
            g_cnt2[ng] = 0u;
            __threadfence();
            g_gen2[ng] = g + 1u;
        } else {
            while (g_gen2[ng] == g) __nanosleep(50);
        }
        __threadfence();
    }
    __syncthreads();
}

// ---------------- persistent tf32-MMA recurrence ----------------
// Grid 128 = mg(32) x ng(4). Per block: 16 hcols x 4 gates (M=64 of 2048),
// 32 batches (N), full K=512. C = R @ h^T via m16n8k8 tf32 MMA.
// R pre-arranged in smem in A-fragment order; h exchanged via g_hP in
// B-fragment order (written by producer, read with __ldcg).
__global__ void __launch_bounds__(256, 1)
lstm_rec(const float* __restrict__ h0, const float* __restrict__ c0,
         const float* __restrict__ Ri, const float* __restrict__ Rf,
         const float* __restrict__ Rg, const float* __restrict__ Ro,
         float* __restrict__ out)
{
    extern __shared__ float smem[];
    uint4* Ra   = (uint4*)smem;          // [4 mt][64 ks][32 lane] uint4 = 131072 B
    float* buf  = smem + 32768;          // [64][33] = 8448 floats

    const int tid  = threadIdx.x;
    const int lane = tid & 31;
    const int w    = tid >> 5;
    const int wm   = w >> 1;             // m16 tile 0..3
    const int wn   = w & 1;              // n half
    const int gid  = lane >> 2;
    const int tig  = lane & 3;

    const int mg = blockIdx.x & 31;
    const int ng = blockIdx.x >> 5;
    const int M0    = mg * 64;           // mcol base (mcol = hcol*4+gate)
    const int hcol0 = mg * 16;
    const int batch0 = ng * 32;

    // ---- arrange R into A-fragment order (one-time) ----
    const float* Rp0 = Ri; const float* Rp1 = Rf;
    const float* Rp2 = Rg; const float* Rp3 = Ro;
#pragma unroll 1
    for (int i = 0; i < 32; i++) {
        const int idx = tid + i * 256;
        const int mt = idx >> 11, ks = (idx >> 5) & 63, ln = idx & 31;
        const int g2 = ln >> 2, t2 = ln & 3;
        const int r0 = M0 + mt * 16 + g2, r1 = r0 + 8;
        const int k0 = ks * 8 + t2;
        const float* P0 = ((r0 & 3) == 0) ? Rp0 : ((r0 & 3) == 1) ? Rp1 : ((r0 & 3) == 2) ? Rp2 : Rp3;
        const float* P1 = ((r1 & 3) == 0) ? Rp0 : ((r1 & 3) == 1) ? Rp1 : ((r1 & 3) == 2) ? Rp2 : Rp3;
        const size_t o0 = (size_t)(r0 >> 2) * H_;
        const size_t o1 = (size_t)(r1 >> 2) * H_;
        uint4 v;
        v.x = tf32_(P0[o0 + k0]);
        v.y = tf32_(P1[o1 + k0]);
        v.z = tf32_(P0[o0 + k0 + 4]);
        v.w = tf32_(P1[o1 + k0 + 4]);
        Ra[idx] = v;
    }

    // ---- init c state + hP buffer 0 ----
    const int bl  = tid >> 3;            // 0..31 local batch
    const int hl0 = (tid & 7) * 2;       // local hcol (pair)
    float creg[2];
#pragma unroll
    for (int q = 0; q < 2; q++) {
        const int j = hcol0 + hl0 + q;
        const int b = batch0 + bl;
        creg[q] = c0[(size_t)b * H_ + j];
        const float hv = h0[(size_t)b * H_ + j];
        const size_t hidx = (((size_t)(b >> 3) * 64 + (j >> 3)) * 32 + ((b & 7) * 4 + (j & 3))) * 2 + ((j >> 2) & 1);
        g_hP[hidx] = __uint_as_float(tf32_(hv));
    }
    __threadfence();

    const uint4* RaW = Ra + wm * 64 * 32;
    const int bnA = ng * 4 + wn * 2;     // global n8-tile for j=0
    const size_t BTH = (size_t)B_ * T_ * H_;
    const int r0r = wm * 16 + gid;       // local m-row of c0/c1

    for (int t = 0; t < T_; t++) {
        __syncthreads();   // protect buf reuse vs previous cell update

        // ---- cooperative gate load (coalesced float4 x2) -> buf ----
        {
            const int i0 = tid * 8;
            const int gbl = i0 >> 6, gga = (i0 >> 4) & 3, ghl = i0 & 15;
            const float* gp = g_gates + (((size_t)t * B_ + (batch0 + gbl)) * 4 + gga) * H_ + hcol0 + ghl;
            float4 u0 = *(const float4*)gp;
            float4 u1 = *(const float4*)(gp + 4);
            const int rowb = (ghl * 4 + gga);
            buf[(rowb + 0)  * 33 + gbl] = u0.x;
            buf[(rowb + 4)  * 33 + gbl] = u0.y;
            buf[(rowb + 8)  * 33 + gbl] = u0.z;
            buf[(rowb + 12) * 33 + gbl] = u0.w;
            buf[(rowb + 16) * 33 + gbl] = u1.x;
            buf[(rowb + 20) * 33 + gbl] = u1.y;
            buf[(rowb + 24) * 33 + gbl] = u1.z;
            buf[(rowb + 28) * 33 + gbl] = u1.w;
        }

        group_barrier32(ng);             // hP[t&1] fully written by peer blocks

        // ---- MMA: acc[j] = (R @ h^T) tile ----
        float acc[2][4];
#pragma unroll
        for (int j = 0; j < 2; j++)
#pragma unroll
            for (int r = 0; r < 4; r++) acc[j][r] = 0.0f;

        const float2* hp = (const float2*)g_hP + (size_t)(t & 1) * (16 * 64 * 32);
#pragma unroll 8
        for (int ks = 0; ks < 64; ks++) {
            uint4 a = RaW[ks * 32 + lane];
            float2 bf0 = __ldcg(&hp[((size_t)bnA * 64 + ks) * 32 + lane]);
            float2 bf1 = __ldcg(&hp[((size_t)(bnA + 1) * 64 + ks) * 32 + lane]);
            mma_tf32(acc[0], (const unsigned*)&a, __float_as_uint(bf0.x), __float_as_uint(bf0.y));
            mma_tf32(acc[1], (const unsigned*)&a, __float_as_uint(bf1.x), __float_as_uint(bf1.y));
        }

        // ---- add x-gate pre-activations from buf ----
#pragma unroll
        for (int j = 0; j < 2; j++) {
            const int cn = (wn * 2 + j) * 8 + tig * 2;
            acc[j][0] += buf[r0r * 33 + cn];
            acc[j][1] += buf[r0r * 33 + cn + 1];
            acc[j][2] += buf[(r0r + 8) * 33 + cn];
            acc[j][3] += buf[(r0r + 8) * 33 + cn + 1];
        }
        __syncthreads();

        // ---- store full pre-activations back to buf ----
#pragma unroll
        for (int j = 0; j < 2; j++) {
            const int cn = (wn * 2 + j) * 8 + tig * 2;
            buf[r0r * 33 + cn]           = acc[j][0];
            buf[r0r * 33 + cn + 1]       = acc[j][1];
            buf[(r0r + 8) * 33 + cn]     = acc[j][2];
            buf[(r0r + 8) * 33 + cn + 1] = acc[j][3];
        }
        __syncthreads();

        // ---- LSTM cell update (2 cells per thread) ----
#pragma unroll
        for (int q = 0; q < 2; q++) {
            const int hl = hl0 + q;
            const int j  = hcol0 + hl;
            const int b  = batch0 + bl;
            const float pi = buf[(hl * 4 + 0) * 33 + bl];
            const float pf = buf[(hl * 4 + 1) * 33 + bl];
            const float pg = buf[(hl * 4 + 2) * 33 + bl];
            const float po = buf[(hl * 4 + 3) * 33 + bl];
            const float ig = sigmoidf_(pi);
            const float fg = sigmoidf_(pf);
            const float gg = tanhf(pg);
            const float og = sigmoidf_(po);
            const float cn2 = gg * ig + fg * creg[q];
            creg[q] = cn2;
            const float hn = og * tanhf(cn2);

            out[(size_t)b * (T_ * H_) + (size_t)t * H_ + j] = hn;
            const size_t hidx = ((size_t)((t + 1) & 1) * 16 * 64 * 32
                                 + ((size_t)(b >> 3) * 64 + (j >> 3)) * 32
                                 + ((b & 7) * 4 + (j & 3))) * 2 + ((j >> 2) & 1);
            g_hP[hidx] = __uint_as_float(tf32_(hn));
            if (t == T_ - 1) {
                out[BTH + (size_t)b * H_ + j] = hn;
                out[BTH + (size_t)(B_ * H_) + (size_t)b * H_ + j] = cn2;
            }
        }
        __threadfence();   // order hP[t+1] writes before next barrier arrival
    }
}

// ---------------- launch ----------------
extern "C" void kernel_launch(void* const* d_in, const int* in_sizes, int n_in,
                              void* d_out, int out_size)
{
    (void)in_sizes; (void)n_in; (void)out_size;
    const float* x  = (const float*)d_in[0];
    const float* h0 = (const float*)d_in[1];
    const float* c0 = (const float*)d_in[2];
    const float* We = (const float*)d_in[3];
    const float* be = (const float*)d_in[4];
    const float* Wf = (const float*)d_in[5];
    const float* bf = (const float*)d_in[6];
    const float* Wi = (const float*)d_in[7];
    const float* bi = (const float*)d_in[8];
    const float* Wg = (const float*)d_in[9];
    const float* bg = (const float*)d_in[10];
    const float* Wo = (const float*)d_in[11];
    const float* bo = (const float*)d_in[12];
    const float* Rf = (const float*)d_in[13];
    const float* Ri = (const float*)d_in[14];
    const float* Rg = (const float*)d_in[15];
    const float* Ro = (const float*)d_in[16];
    float* out = (float*)d_out;

    static bool attr_set = false;
    if (!attr_set) {
        cudaFuncSetAttribute(lstm_rec,
                             cudaFuncAttributeMaxDynamicSharedMemorySize, 165888);
        attr_set = true;
    }

    // xe = x @ We^T + be
    dim3 g1(E_ / 128, (B_ * T_) / 128, 1);
    sgemm_bias<0><<<g1, 256>>>(x, We, We, We, We, be, be, be, be, DIM_);

    // gate pre-activations (i,f,g,o), layout [t][b][gate][hcol]
    dim3 g2(H_ / 128, (B_ * T_) / 128, 4);
    sgemm_bias<1><<<g2, 256>>>(nullptr, Wi, Wf, Wg, Wo, bi, bf, bg, bo, E_);

    // persistent tf32 recurrence (gate order i,f,g,o)
    const int dynsmem = (32768 + 64 * 33) * 4;   // Ra + buf = 139520 B
    lstm_rec<<<128, 256, dynsmem>>>(h0, c0, Ri, Rf, Rg, Ro, out);
}

// round 3
// speedup vs baseline: 2.5111x; 1.5647x over previous
#include <cuda_runtime.h>
#include <cstdint>

#define B_   128
#define T_   512
#define DIM_ 256
#define E_   512
#define H_   512

// ---------------- device scratch ----------------
__device__ float g_xe[(size_t)B_ * T_ * E_];          // [m=b*T+t][e]
__device__ float g_gates[(size_t)T_ * B_ * 2048];     // [t][b][mcol], mcol = hcol*4+gate
__device__ float g_Wall[2048 * 512];                  // packed gate weights, row = mcol
__device__ float g_ball[2048];
__device__ float g_hP[2 * 16 * 64 * 32 * 2];          // [buf][bn][ks][lane][2] (tf32 bits)
__device__ unsigned g_cnt2[4];
__device__ volatile unsigned g_gen2[4];

// ---------------- helpers ----------------
__device__ __forceinline__ unsigned tf32_(float f) {
    unsigned u;
    asm("cvt.rna.tf32.f32 %0, %1;" : "=r"(u) : "f"(f));
    return u;
}
__device__ __forceinline__ float tf32f_(float f) {
    return __uint_as_float(tf32_(f));
}

__device__ __forceinline__ void mma_tf32(float* d, const unsigned* a, unsigned b0, unsigned b1) {
    asm volatile(
        "mma.sync.aligned.m16n8k8.row.col.f32.tf32.tf32.f32 "
        "{%0,%1,%2,%3}, {%4,%5,%6,%7}, {%8,%9}, {%0,%1,%2,%3};"
        : "+f"(d[0]), "+f"(d[1]), "+f"(d[2]), "+f"(d[3])
        : "r"(a[0]), "r"(a[1]), "r"(a[2]), "r"(a[3]), "r"(b0), "r"(b1));
}

__device__ __forceinline__ float sigmoidf_(float x) {
    return 1.0f / (1.0f + __expf(-x));
}

// ---------------- pack gate weights: row mcol = hcol*4+gate ----------------
__global__ void __launch_bounds__(256)
pack_w(const float* __restrict__ Wi, const float* __restrict__ Wf,
       const float* __restrict__ Wg, const float* __restrict__ Wo,
       const float* __restrict__ bi, const float* __restrict__ bf,
       const float* __restrict__ bg, const float* __restrict__ bo)
{
    const int idx = blockIdx.x * 256 + threadIdx.x;   // 2048*128 float4s
    const int n = idx >> 7, kq = idx & 127;
    const int gate = n & 3, hc = n >> 2;
    const float* W = (gate == 0) ? Wi : (gate == 1) ? Wf : (gate == 2) ? Wg : Wo;
    float4 v = *(const float4*)(W + (size_t)hc * 512 + kq * 4);
    *(float4*)(g_Wall + (size_t)n * 512 + kq * 4) = v;
    if (kq == 0) {
        const float* bb = (gate == 0) ? bi : (gate == 1) ? bf : (gate == 2) ? bg : bo;
        g_ball[n] = bb[hc];
    }
}

// ---------------- tf32 MMA GEMM: C = A @ W^T + bias ----------------
// 128x128 block tile, BK=32, 128 threads (4 warps, 64x64 warp tiles).
// MODE 0: A param (x), W param (We), out -> g_xe[m][n]  (KDIM=256, N=512)
// MODE 1: A = g_xe, W = g_Wall, out -> g_gates[t][b][n]  (KDIM=512, N=2048)
template <int KDIM, int MODE>
__global__ void __launch_bounds__(128)
gemm_tf32(const float* __restrict__ A_, const float* __restrict__ W_,
          const float* __restrict__ bias_)
{
    __shared__ float As[128 * 36];
    __shared__ float Ws[128 * 36];

    const float* A    = (MODE == 0) ? A_    : g_xe;
    const float* W    = (MODE == 0) ? W_    : g_Wall;
    const float* bias = (MODE == 0) ? bias_ : g_ball;

    const int tid = threadIdx.x, lane = tid & 31, warp = tid >> 5;
    const int wm = warp >> 1, wn = warp & 1;
    const int m0 = blockIdx.y * 128, n0 = blockIdx.x * 128;

    const int rb = tid >> 3;        // staging base row (0..15)
    const int kq = tid & 7;         // staging k-quad
    const float* Ag = A + (size_t)(m0 + rb) * KDIM + kq * 4;
    const float* Wgp = W + (size_t)(n0 + rb) * KDIM + kq * 4;

    float4 pa[8], pw[8];
#pragma unroll
    for (int p = 0; p < 8; p++) {
        pa[p] = *(const float4*)(Ag  + (size_t)(16 * p) * KDIM);
        pw[p] = *(const float4*)(Wgp + (size_t)(16 * p) * KDIM);
    }

    float acc[4][8][4];
#pragma unroll
    for (int mt = 0; mt < 4; mt++)
#pragma unroll
        for (int nt = 0; nt < 8; nt++)
#pragma unroll
            for (int r = 0; r < 4; r++) acc[mt][nt][r] = 0.0f;

    const int g = lane >> 2, t = lane & 3;

    for (int kk = 0; kk < KDIM; kk += 32) {
#pragma unroll
        for (int p = 0; p < 8; p++) {
            const int ro = (rb + 16 * p) * 36 + kq * 4;
            float4 a = pa[p], w = pw[p];
            *(float4*)(As + ro) = make_float4(tf32f_(a.x), tf32f_(a.y), tf32f_(a.z), tf32f_(a.w));
            *(float4*)(Ws + ro) = make_float4(tf32f_(w.x), tf32f_(w.y), tf32f_(w.z), tf32f_(w.w));
        }
        __syncthreads();

        if (kk + 32 < KDIM) {
#pragma unroll
            for (int p = 0; p < 8; p++) {
                pa[p] = *(const float4*)(Ag  + (kk + 32) + (size_t)(16 * p) * KDIM);
                pw[p] = *(const float4*)(Wgp + (kk + 32) + (size_t)(16 * p) * KDIM);
            }
        }

#pragma unroll
        for (int s = 0; s < 4; s++) {
            unsigned af[4][4], bf[8][2];
#pragma unroll
            for (int mt = 0; mt < 4; mt++) {
                const int r = (wm * 64 + mt * 16 + g) * 36 + s * 8 + t;
                af[mt][0] = __float_as_uint(As[r]);
                af[mt][1] = __float_as_uint(As[r + 8 * 36]);
                af[mt][2] = __float_as_uint(As[r + 4]);
                af[mt][3] = __float_as_uint(As[r + 8 * 36 + 4]);
            }
#pragma unroll
            for (int nt = 0; nt < 8; nt++) {
                const int r = (wn * 64 + nt * 8 + g) * 36 + s * 8 + t;
                bf[nt][0] = __float_as_uint(Ws[r]);
                bf[nt][1] = __float_as_uint(Ws[r + 4]);
            }
#pragma unroll
            for (int mt = 0; mt < 4; mt++)
#pragma unroll
                for (int nt = 0; nt < 8; nt++)
                    mma_tf32(acc[mt][nt], af[mt], bf[nt][0], bf[nt][1]);
        }
        __syncthreads();
    }

    // ---- epilogue: add bias, store ----
#pragma unroll
    for (int mt = 0; mt < 4; mt++) {
        const int row0 = m0 + wm * 64 + mt * 16 + g;
#pragma unroll
        for (int nt = 0; nt < 8; nt++) {
            const int col = n0 + wn * 64 + nt * 8 + t * 2;
            const float2 bv = *(const float2*)(bias + col);
            float2 v0 = make_float2(acc[mt][nt][0] + bv.x, acc[mt][nt][1] + bv.y);
            float2 v1 = make_float2(acc[mt][nt][2] + bv.x, acc[mt][nt][3] + bv.y);
            if (MODE == 0) {
                *(float2*)(g_xe + (size_t)row0 * E_ + col) = v0;
                *(float2*)(g_xe + (size_t)(row0 + 8) * E_ + col) = v1;
            } else {
                const int b0v = row0 >> 9, t0v = row0 & 511;
                const int b1v = (row0 + 8) >> 9, t1v = (row0 + 8) & 511;
                *(float2*)(g_gates + ((size_t)t0v * B_ + b0v) * 2048 + col) = v0;
                *(float2*)(g_gates + ((size_t)t1v * B_ + b1v) * 2048 + col) = v1;
            }
        }
    }
}

// ---------------- group barrier (32 blocks per batch-group) ----------------
__device__ __forceinline__ void group_barrier32(int ng) {
    __syncthreads();
    if (threadIdx.x == 0) {
        unsigned g = g_gen2[ng];
        __threadfence();
        unsigned old = atomicAdd(&g_cnt2[ng], 1u);
        if (old == 31u) {
            g_cnt2[ng] = 0u;
            __threadfence();
            g_gen2[ng] = g + 1u;
        } else {
            while (g_gen2[ng] == g) __nanosleep(20);
        }
        __threadfence();
    }
    __syncthreads();
}

// ---------------- persistent tf32-MMA recurrence ----------------
__global__ void __launch_bounds__(256, 1)
lstm_rec(const float* __restrict__ h0, const float* __restrict__ c0,
         const float* __restrict__ Ri, const float* __restrict__ Rf,
         const float* __restrict__ Rg, const float* __restrict__ Ro,
         float* __restrict__ out)
{
    extern __shared__ float smem[];
    uint4* Ra  = (uint4*)smem;           // [4 mt][64 ks][32 lane] uint4 = 131072 B
    float* buf = smem + 32768;           // [64][33]

    const int tid  = threadIdx.x;
    const int lane = tid & 31;
    const int w    = tid >> 5;
    const int wm   = w >> 1;
    const int wn   = w & 1;
    const int gid  = lane >> 2;
    const int tig  = lane & 3;

    const int mg = blockIdx.x & 31;
    const int ng = blockIdx.x >> 5;
    const int M0 = mg * 64;
    const int hcol0 = mg * 16;
    const int batch0 = ng * 32;

    // ---- arrange R into A-fragment order (one-time) ----
    const float* Rp0 = Ri; const float* Rp1 = Rf;
    const float* Rp2 = Rg; const float* Rp3 = Ro;
#pragma unroll 1
    for (int i = 0; i < 32; i++) {
        const int idx = tid + i * 256;
        const int mt = idx >> 11, ks = (idx >> 5) & 63, ln = idx & 31;
        const int g2 = ln >> 2, t2 = ln & 3;
        const int r0 = M0 + mt * 16 + g2, r1 = r0 + 8;
        const int k0 = ks * 8 + t2;
        const float* P0 = ((r0 & 3) == 0) ? Rp0 : ((r0 & 3) == 1) ? Rp1 : ((r0 & 3) == 2) ? Rp2 : Rp3;
        const float* P1 = ((r1 & 3) == 0) ? Rp0 : ((r1 & 3) == 1) ? Rp1 : ((r1 & 3) == 2) ? Rp2 : Rp3;
        const size_t o0 = (size_t)(r0 >> 2) * H_;
        const size_t o1 = (size_t)(r1 >> 2) * H_;
        uint4 v;
        v.x = tf32_(P0[o0 + k0]);
        v.y = tf32_(P1[o1 + k0]);
        v.z = tf32_(P0[o0 + k0 + 4]);
        v.w = tf32_(P1[o1 + k0 + 4]);
        Ra[idx] = v;
    }

    // ---- init c state + hP buffer 0 ----
    const int bl  = tid >> 3;
    const int hl0 = (tid & 7) * 2;
    float creg[2];
#pragma unroll
    for (int q = 0; q < 2; q++) {
        const int j = hcol0 + hl0 + q;
        const int b = batch0 + bl;
        creg[q] = c0[(size_t)b * H_ + j];
        const float hv = h0[(size_t)b * H_ + j];
        const size_t hidx = (((size_t)(b >> 3) * 64 + (j >> 3)) * 32 + ((b & 7) * 4 + (j & 3))) * 2 + ((j >> 2) & 1);
        g_hP[hidx] = __uint_as_float(tf32_(hv));
    }
    __threadfence();

    const uint4* RaW = Ra + wm * 64 * 32;
    const int bnA = ng * 4 + wn * 2;
    const size_t BTH = (size_t)B_ * T_ * H_;
    const int r0r = wm * 16 + gid;

    for (int t = 0; t < T_; t++) {
        __syncthreads();

        // ---- cooperative gate load: 8 consecutive mcols/thread -> buf ----
        {
            const int gbl = tid >> 3;            // local batch 0..31
            const int ml  = (tid & 7) * 8;       // local mcol base
            const float* gp = g_gates + ((size_t)t * B_ + (batch0 + gbl)) * 2048 + M0 + ml;
            float4 u0 = *(const float4*)gp;
            float4 u1 = *(const float4*)(gp + 4);
            buf[(ml + 0) * 33 + gbl] = u0.x;
            buf[(ml + 1) * 33 + gbl] = u0.y;
            buf[(ml + 2) * 33 + gbl] = u0.z;
            buf[(ml + 3) * 33 + gbl] = u0.w;
            buf[(ml + 4) * 33 + gbl] = u1.x;
            buf[(ml + 5) * 33 + gbl] = u1.y;
            buf[(ml + 6) * 33 + gbl] = u1.z;
            buf[(ml + 7) * 33 + gbl] = u1.w;
        }

        group_barrier32(ng);

        // ---- MMA: acc[j] = (R @ h^T) tile ----
        float acc[2][4];
#pragma unroll
        for (int j = 0; j < 2; j++)
#pragma unroll
            for (int r = 0; r < 4; r++) acc[j][r] = 0.0f;

        const float2* hp = (const float2*)g_hP + (size_t)(t & 1) * (16 * 64 * 32);
#pragma unroll 8
        for (int ks = 0; ks < 64; ks++) {
            uint4 a = RaW[ks * 32 + lane];
            float2 bf0 = __ldcg(&hp[((size_t)bnA * 64 + ks) * 32 + lane]);
            float2 bf1 = __ldcg(&hp[((size_t)(bnA + 1) * 64 + ks) * 32 + lane]);
            mma_tf32(acc[0], (const unsigned*)&a, __float_as_uint(bf0.x), __float_as_uint(bf0.y));
            mma_tf32(acc[1], (const unsigned*)&a, __float_as_uint(bf1.x), __float_as_uint(bf1.y));
        }

        // ---- add x-gate pre-activations ----
#pragma unroll
        for (int j = 0; j < 2; j++) {
            const int cn = (wn * 2 + j) * 8 + tig * 2;
            acc[j][0] += buf[r0r * 33 + cn];
            acc[j][1] += buf[r0r * 33 + cn + 1];
            acc[j][2] += buf[(r0r + 8) * 33 + cn];
            acc[j][3] += buf[(r0r + 8) * 33 + cn + 1];
        }
        __syncthreads();

#pragma unroll
        for (int j = 0; j < 2; j++) {
            const int cn = (wn * 2 + j) * 8 + tig * 2;
            buf[r0r * 33 + cn]           = acc[j][0];
            buf[r0r * 33 + cn + 1]       = acc[j][1];
            buf[(r0r + 8) * 33 + cn]     = acc[j][2];
            buf[(r0r + 8) * 33 + cn + 1] = acc[j][3];
        }
        __syncthreads();

        // ---- LSTM cell update ----
#pragma unroll
        for (int q = 0; q < 2; q++) {
            const int hl = hl0 + q;
            const int j  = hcol0 + hl;
            const int b  = batch0 + bl;
            const float pi = buf[(hl * 4 + 0) * 33 + bl];
            const float pf = buf[(hl * 4 + 1) * 33 + bl];
            const float pg = buf[(hl * 4 + 2) * 33 + bl];
            const float po = buf[(hl * 4 + 3) * 33 + bl];
            const float ig = sigmoidf_(pi);
            const float fg = sigmoidf_(pf);
            const float gg = tanhf(pg);
            const float og = sigmoidf_(po);
            const float cn2 = gg * ig + fg * creg[q];
            creg[q] = cn2;
            const float hn = og * tanhf(cn2);

            out[(size_t)b * (T_ * H_) + (size_t)t * H_ + j] = hn;
            const size_t hidx = ((size_t)((t + 1) & 1) * 16 * 64 * 32
                                 + ((size_t)(b >> 3) * 64 + (j >> 3)) * 32
                                 + ((b & 7) * 4 + (j & 3))) * 2 + ((j >> 2) & 1);
            g_hP[hidx] = __uint_as_float(tf32_(hn));
            if (t == T_ - 1) {
                out[BTH + (size_t)b * H_ + j] = hn;
                out[BTH + (size_t)(B_ * H_) + (size_t)b * H_ + j] = cn2;
            }
        }
        __threadfence();
    }
}

// ---------------- launch ----------------
extern "C" void kernel_launch(void* const* d_in, const int* in_sizes, int n_in,
                              void* d_out, int out_size)
{
    (void)in_sizes; (void)n_in; (void)out_size;
    const float* x  = (const float*)d_in[0];
    const float* h0 = (const float*)d_in[1];
    const float* c0 = (const float*)d_in[2];
    const float* We = (const float*)d_in[3];
    const float* be = (const float*)d_in[4];
    const float* Wf = (const float*)d_in[5];
    const float* bf = (const float*)d_in[6];
    const float* Wi = (const float*)d_in[7];
    const float* bi = (const float*)d_in[8];
    const float* Wg = (const float*)d_in[9];
    const float* bg = (const float*)d_in[10];
    const float* Wo = (const float*)d_in[11];
    const float* bo = (const float*)d_in[12];
    const float* Rf = (const float*)d_in[13];
    const float* Ri = (const float*)d_in[14];
    const float* Rg = (const float*)d_in[15];
    const float* Ro = (const float*)d_in[16];
    float* out = (float*)d_out;

    static bool attr_set = false;
    if (!attr_set) {
        cudaFuncSetAttribute(lstm_rec,
                             cudaFuncAttributeMaxDynamicSharedMemorySize, 165888);
        attr_set = true;
    }

    // pack gate weights (i,f,g,o interleaved by mcol)
    pack_w<<<1024, 256>>>(Wi, Wf, Wg, Wo, bi, bf, bg, bo);

    // xe = x @ We^T + be  (tf32 MMA)
    gemm_tf32<DIM_, 0><<<dim3(E_ / 128, (B_ * T_) / 128), 128>>>(x, We, be);

    // gates = xe @ Wall^T + ball  (tf32 MMA, N=2048)
    gemm_tf32<E_, 1><<<dim3(2048 / 128, (B_ * T_) / 128), 128>>>(nullptr, nullptr, nullptr);

    // persistent tf32 recurrence
    const int dynsmem = (32768 + 64 * 33) * 4;
    lstm_rec<<<128, 256, dynsmem>>>(h0, c0, Ri, Rf, Rg, Ro, out);
}